// round 13
// baseline (speedup 1.0000x reference)
#include <cuda_runtime.h>
#include <cuda_fp16.h>
#include <cstdint>

#define NDIM 128
#define MAX_NODES 100000

// Scratch: fp16 z table, fp16 x_source copy, dtype flag.
__device__ __half g_z_h[MAX_NODES * NDIM];    // 25.6 MB
__device__ __half g_xs_h[MAX_NODES * NDIM];   // 25.6 MB
__device__ int    g_idx_is64;

// ---------------------------------------------------------------------------
// Kernel 1 (fused): tensor-core GEMM  z[m][d] = sum_f xt[m][f] * W[d][f]
//  + block 0: index-dtype detection (int64 values < 2^31 -> odd words all 0)
//  + epilogue: grid-stride convert x_source fp32 -> fp16
// mma.sync.m16n8k16.row.col.f32.f16.f16.f32
// 16 NAMED SCALAR accumulators (register arrays => lmem demotion => 128 MiB
// pool growth => harness violation; scalars proven safe R10-R12).
// Block: 256 thr = 8 warps x 16 rows = 128 rows/block.
// ---------------------------------------------------------------------------
__global__ void __launch_bounds__(256) gemm_fused_kernel(
    const float* __restrict__ xt,
    const float* __restrict__ W,
    const int*   __restrict__ eli_words,  int nwords,
    const float* __restrict__ xs,         int n_elem4,
    int n_rows) {
    __shared__ __half W_sh[NDIM][NDIM + 8];
    __shared__ int s_any_nonzero;

    // --- detect idx dtype (block 0 only) ---
    if (blockIdx.x == 0) {
        if (threadIdx.x == 0) s_any_nonzero = 0;
        __syncthreads();
        for (int i = 1 + 2 * threadIdx.x; i < nwords; i += 2 * blockDim.x) {
            if (eli_words[i] != 0) { s_any_nonzero = 1; break; }
        }
        __syncthreads();
        if (threadIdx.x == 0) g_idx_is64 = (s_any_nonzero == 0) ? 1 : 0;
    }

    // --- stage W into shared (fp16) ---
    for (int i = threadIdx.x; i < NDIM * NDIM; i += 256) {
        int r = i >> 7;
        int c = i & (NDIM - 1);
        W_sh[r][c] = __float2half_rn(W[i]);
    }
    __syncthreads();

    const int warp = threadIdx.x >> 5;
    const int lane = threadIdx.x & 31;
    const int g = lane >> 2;        // 0..7
    const int t = lane & 3;         // 0..3
    const int row_base = blockIdx.x * 128 + warp * 16;

    if (row_base < n_rows) {
        // clamp fragment rows so tail warps never read OOB (stores guarded)
        int r0 = row_base + g;      if (r0 >= n_rows) r0 = n_rows - 1;
        int r1 = row_base + g + 8;  if (r1 >= n_rows) r1 = n_rows - 1;
        const float* A0 = xt + (size_t)r0 * NDIM + 2 * t;
        const float* A1 = xt + (size_t)r1 * NDIM + 2 * t;

        const int row0 = row_base + g;
        const int row1 = row_base + g + 8;

#define LOAD_A(k0, a0, a1, a2, a3)                                       \
    unsigned int a0, a1, a2, a3;                                          \
    {                                                                     \
        float2 f0 = *(const float2*)(A0 + (k0));                          \
        float2 f1 = *(const float2*)(A1 + (k0));                          \
        float2 f2 = *(const float2*)(A0 + (k0) + 8);                      \
        float2 f3 = *(const float2*)(A1 + (k0) + 8);                      \
        __half2 h0 = __floats2half2_rn(f0.x, f0.y);                       \
        __half2 h1 = __floats2half2_rn(f1.x, f1.y);                       \
        __half2 h2 = __floats2half2_rn(f2.x, f2.y);                       \
        __half2 h3 = __floats2half2_rn(f3.x, f3.y);                       \
        a0 = *(unsigned int*)&h0; a1 = *(unsigned int*)&h1;               \
        a2 = *(unsigned int*)&h2; a3 = *(unsigned int*)&h3;               \
    }

#define MMA_STEP(k0, A0r, A1r, A2r, A3r, C0, C1, C2, C3, NROW)                 \
    {                                                                          \
        unsigned int b0 = *(const unsigned int*)&W_sh[(NROW) + g][(k0) + 2 * t]; \
        unsigned int b1 = *(const unsigned int*)&W_sh[(NROW) + g][(k0) + 2 * t + 8]; \
        asm volatile(                                                          \
            "mma.sync.aligned.m16n8k16.row.col.f32.f16.f16.f32 "               \
            "{%0,%1,%2,%3}, {%4,%5,%6,%7}, {%8,%9}, {%0,%1,%2,%3};"            \
            : "+f"(C0), "+f"(C1), "+f"(C2), "+f"(C3)                           \
            : "r"(A0r), "r"(A1r), "r"(A2r), "r"(A3r), "r"(b0), "r"(b1));       \
    }

#pragma unroll 1
        for (int ntg = 0; ntg < 4; ntg++) {
            const int n0 = ntg * 32;
            float c00 = 0.f, c01 = 0.f, c02 = 0.f, c03 = 0.f;
            float c10 = 0.f, c11 = 0.f, c12 = 0.f, c13 = 0.f;
            float c20 = 0.f, c21 = 0.f, c22 = 0.f, c23 = 0.f;
            float c30 = 0.f, c31 = 0.f, c32 = 0.f, c33 = 0.f;

#pragma unroll 1
            for (int k0 = 0; k0 < NDIM; k0 += 32) {
                LOAD_A(k0,      p0, p1, p2, p3)
                LOAD_A(k0 + 16, q0, q1, q2, q3)

                MMA_STEP(k0, p0, p1, p2, p3, c00, c01, c02, c03, n0)
                MMA_STEP(k0, p0, p1, p2, p3, c10, c11, c12, c13, n0 + 8)
                MMA_STEP(k0, p0, p1, p2, p3, c20, c21, c22, c23, n0 + 16)
                MMA_STEP(k0, p0, p1, p2, p3, c30, c31, c32, c33, n0 + 24)

                MMA_STEP(k0 + 16, q0, q1, q2, q3, c00, c01, c02, c03, n0)
                MMA_STEP(k0 + 16, q0, q1, q2, q3, c10, c11, c12, c13, n0 + 8)
                MMA_STEP(k0 + 16, q0, q1, q2, q3, c20, c21, c22, c23, n0 + 16)
                MMA_STEP(k0 + 16, q0, q1, q2, q3, c30, c31, c32, c33, n0 + 24)
            }

            const int colb = n0 + 2 * t;
            if (row0 < n_rows) {
                __half* zp = g_z_h + (size_t)row0 * NDIM;
                *(__half2*)(zp + colb)      = __floats2half2_rn(c00, c01);
                *(__half2*)(zp + colb + 8)  = __floats2half2_rn(c10, c11);
                *(__half2*)(zp + colb + 16) = __floats2half2_rn(c20, c21);
                *(__half2*)(zp + colb + 24) = __floats2half2_rn(c30, c31);
            }
            if (row1 < n_rows) {
                __half* zp = g_z_h + (size_t)row1 * NDIM;
                *(__half2*)(zp + colb)      = __floats2half2_rn(c02, c03);
                *(__half2*)(zp + colb + 8)  = __floats2half2_rn(c12, c13);
                *(__half2*)(zp + colb + 16) = __floats2half2_rn(c22, c23);
                *(__half2*)(zp + colb + 24) = __floats2half2_rn(c32, c33);
            }
        }
#undef LOAD_A
#undef MMA_STEP
    }

    // --- epilogue: convert x_source -> fp16 (grid-stride, all blocks) ---
    const int stride = gridDim.x * 256;
    for (int i = blockIdx.x * 256 + threadIdx.x; i < n_elem4; i += stride) {
        float4 v = *(const float4*)(xs + (size_t)i * 4);
        *(__half2*)(g_xs_h + (size_t)i * 4)     = __floats2half2_rn(v.x, v.y);
        *(__half2*)(g_xs_h + (size_t)i * 4 + 2) = __floats2half2_rn(v.z, v.w);
    }
}

// ---------------------------------------------------------------------------
// Kernel 2: per-edge dot on fp16 tables (unchanged from the 155.6us pass).
// ---------------------------------------------------------------------------
__device__ __forceinline__ float dot8h(float4 a, float4 v) {
    const __half2* ah = (const __half2*)&a;
    const __half2* vh = (const __half2*)&v;
    __half2 p0 = __hmul2(ah[0], vh[0]);
    __half2 p1 = __hmul2(ah[1], vh[1]);
    __half2 p2 = __hmul2(ah[2], vh[2]);
    __half2 p3 = __hmul2(ah[3], vh[3]);
    float2 q0 = __half22float2(p0);
    float2 q1 = __half22float2(p1);
    float2 q2 = __half22float2(p2);
    float2 q3 = __half22float2(p3);
    return ((q0.x + q0.y) + (q1.x + q1.y)) + ((q2.x + q2.y) + (q3.x + q3.y));
}

#define EDGES_PER_WARP 8

__global__ void __launch_bounds__(256) edge_dot_kernel(
    const void* __restrict__ eli_raw,
    const float* __restrict__ bias,
    float* __restrict__ out,
    int E, unsigned int Nm1) {
    const int gwarp = (blockIdx.x * blockDim.x + threadIdx.x) >> 5;
    const int lane  = threadIdx.x & 31;
    const int half  = lane >> 4;
    const int sub   = lane & 15;

    const int e0 = gwarp * EDGES_PER_WARP;
    if (e0 >= E) return;

    const int is64 = g_idx_is64;
    const long long* eli64 = (const long long*)eli_raw;
    const int*       eli32 = (const int*)eli_raw;

    unsigned int sIdx[4], tIdx[4];
    int eidx[4];
#pragma unroll
    for (int j = 0; j < 4; j++) {
        int e = min(e0 + 2 * j + half, E - 1);   // tail-safe duplicate work
        eidx[j] = e;
        unsigned int s, t;
        if (is64) {
            s = (unsigned int)__ldg(&eli64[e]);
            t = (unsigned int)__ldg(&eli64[(long long)E + e]);
        } else {
            s = (unsigned int)__ldg(&eli32[e]);
            t = (unsigned int)__ldg(&eli32[(long long)E + e]);
        }
        sIdx[j] = min(s, Nm1);
        tIdx[j] = min(t, Nm1);
    }

    float4 a[4], v[4];
#pragma unroll
    for (int j = 0; j < 4; j++) {
        a[j] = __ldg((const float4*)(g_xs_h + ((size_t)sIdx[j] << 7) + (sub << 3)));
        v[j] = __ldg((const float4*)(g_z_h  + ((size_t)tIdx[j] << 7) + (sub << 3)));
    }

    const float bv = __ldg(bias);

#pragma unroll
    for (int j = 0; j < 4; j++) {
        float acc = dot8h(a[j], v[j]);
#pragma unroll
        for (int o = 8; o > 0; o >>= 1)
            acc += __shfl_down_sync(0xFFFFFFFFu, acc, o, 16);
        if (sub == 0)
            out[eidx[j]] = acc + bv;   // tail duplicates write identical values
    }
}

// ---------------------------------------------------------------------------
extern "C" void kernel_launch(void* const* d_in, const int* in_sizes, int n_in,
                              void* d_out, int out_size) {
    const float* x_source = nullptr;
    const float* x_target = nullptr;
    const void*  eli      = nullptr;
    const float* W        = nullptr;
    const float* bias     = nullptr;
    int N = 0;
    const int E = out_size;

    for (int i = 0; i < n_in; i++) {
        int sz = in_sizes[i];
        if (sz == NDIM * NDIM)      W    = (const float*)d_in[i];
        else if (sz == 1)           bias = (const float*)d_in[i];
        else if (sz == 2 * E)       eli  = d_in[i];
        else {
            if (!x_source) { x_source = (const float*)d_in[i]; N = sz / NDIM; }
            else           { x_target = (const float*)d_in[i]; }
        }
    }

    float* out = (float*)d_out;

    int nwords = 2 * E; if (nwords > 4096) nwords = 4096;
    int n_elem4 = (N * NDIM) / 4;

    // 1) fused: detect idx dtype + z = xt @ W^T (tensor cores) + xs -> fp16
    gemm_fused_kernel<<<(N + 127) / 128, 256>>>(x_target, W,
                                                (const int*)eli, nwords,
                                                x_source, n_elem4, N);

    // 2) per-edge gather + dot
    int warps_needed = (E + EDGES_PER_WARP - 1) / EDGES_PER_WARP;
    int nblocks = (warps_needed + 7) / 8;
    edge_dot_kernel<<<nblocks, 256>>>(eli, bias, out, E, (unsigned int)(N - 1));
}

// round 14
// speedup vs baseline: 1.1202x; 1.1202x over previous
#include <cuda_runtime.h>
#include <cuda_fp16.h>
#include <cstdint>

#define NDIM 128
#define MAX_NODES 100000
#define APAD 136   // smem row stride in halves (128 + 8): conflict-free fragments

// Scratch: fp16 z table, fp16 x_source copy, dtype flag.
__device__ __half g_z_h[MAX_NODES * NDIM];    // 25.6 MB
__device__ __half g_xs_h[MAX_NODES * NDIM];   // 25.6 MB
__device__ int    g_idx_is64;

// ---------------------------------------------------------------------------
// Kernel 0: detect index dtype (int64 values < 2^31 -> all odd words zero).
// ---------------------------------------------------------------------------
__global__ void detect_idx_kernel(const int* __restrict__ idx_words, int nwords) {
    __shared__ int s_any_nonzero;
    if (threadIdx.x == 0) s_any_nonzero = 0;
    __syncthreads();
    for (int i = 1 + 2 * threadIdx.x; i < nwords; i += 2 * blockDim.x) {
        if (idx_words[i] != 0) { s_any_nonzero = 1; break; }
    }
    __syncthreads();
    if (threadIdx.x == 0) g_idx_is64 = (s_any_nonzero == 0) ? 1 : 0;
}

// ---------------------------------------------------------------------------
// Kernel 1: convert x_source -> fp16 (vectorized x4)
// ---------------------------------------------------------------------------
__global__ void __launch_bounds__(256) convert_xs_kernel(const float* __restrict__ xs,
                                                         int n_elem4) {
    int i = blockIdx.x * blockDim.x + threadIdx.x;
    if (i >= n_elem4) return;
    float4 v = *(const float4*)(xs + (size_t)i * 4);
    *(__half2*)(g_xs_h + (size_t)i * 4)     = __floats2half2_rn(v.x, v.y);
    *(__half2*)(g_xs_h + (size_t)i * 4 + 2) = __floats2half2_rn(v.z, v.w);
}

// ---------------------------------------------------------------------------
// Kernel 2: tensor-core GEMM  z[m][d] = sum_f xt[m][f] * W[d][f]
// mma.sync.m16n8k16.row.col.f32.f16.f16.f32
// NEW vs R12: A tile STAGED in shared via bulk coalesced float4 loads
// (16 LDG.128/thread, MLP 16 -> DRAM-streaming instead of latency-bound).
// Fragments then come from LDS (bank = (4g+t) mod 32, conflict-free).
// 16 NAMED SCALAR accumulators (register arrays => lmem => 128MiB violation).
// Dynamic smem: A[128][136] + W[128][136] fp16 = 68 KB.
// Block: 256 thr = 8 warps x 16 rows = 128 rows/block.
// ---------------------------------------------------------------------------
__global__ void __launch_bounds__(256) gemm_mma_kernel(const float* __restrict__ xt,
                                                       const float* __restrict__ W,
                                                       int n_rows) {
    extern __shared__ __half smem[];
    __half* A_sh = smem;                 // [128][APAD]
    __half* W_sh = smem + NDIM * APAD;   // [128][APAD]

    const int tid = threadIdx.x;
    const int block_base = blockIdx.x * 128;

    // --- stage W (fp32 -> fp16) ---
    for (int i = tid; i < NDIM * NDIM; i += 256) {
        int r = i >> 7;
        int c = i & (NDIM - 1);
        W_sh[r * APAD + c] = __float2half_rn(W[i]);
    }

    // --- stage A tile: 128 rows x 32 float4 = 4096 chunks, 16 per thread ---
#pragma unroll 4
    for (int i = tid; i < 128 * 32; i += 256) {
        int r  = i >> 5;          // local row 0..127
        int c4 = i & 31;          // float4 index 0..31
        int grow = block_base + r;
        if (grow >= n_rows) grow = n_rows - 1;   // clamp (stores guarded later)
        float4 v = *(const float4*)(xt + (size_t)grow * NDIM + c4 * 4);
        __half2 h0 = __floats2half2_rn(v.x, v.y);
        __half2 h1 = __floats2half2_rn(v.z, v.w);
        __half* p = A_sh + r * APAD + c4 * 4;
        *(__half2*)(p)     = h0;
        *(__half2*)(p + 2) = h1;
    }
    __syncthreads();

    const int warp = tid >> 5;
    const int lane = tid & 31;
    const int g = lane >> 2;        // 0..7
    const int t = lane & 3;         // 0..3
    const int row_base = block_base + warp * 16;
    if (row_base >= n_rows) return;

    const __half* Arow0 = A_sh + (warp * 16 + g)     * APAD + 2 * t;
    const __half* Arow1 = A_sh + (warp * 16 + g + 8) * APAD + 2 * t;
    const int row0 = row_base + g;
    const int row1 = row_base + g + 8;

#define LOAD_A(k0, a0, a1, a2, a3)                                   \
    unsigned int a0, a1, a2, a3;                                      \
    {                                                                 \
        a0 = *(const unsigned int*)(Arow0 + (k0));                    \
        a1 = *(const unsigned int*)(Arow1 + (k0));                    \
        a2 = *(const unsigned int*)(Arow0 + (k0) + 8);                \
        a3 = *(const unsigned int*)(Arow1 + (k0) + 8);                \
    }

#define MMA_STEP(k0, A0r, A1r, A2r, A3r, C0, C1, C2, C3, NROW)                    \
    {                                                                             \
        unsigned int b0 = *(const unsigned int*)(W_sh + ((NROW) + g) * APAD + (k0) + 2 * t);     \
        unsigned int b1 = *(const unsigned int*)(W_sh + ((NROW) + g) * APAD + (k0) + 2 * t + 8); \
        asm volatile(                                                             \
            "mma.sync.aligned.m16n8k16.row.col.f32.f16.f16.f32 "                  \
            "{%0,%1,%2,%3}, {%4,%5,%6,%7}, {%8,%9}, {%0,%1,%2,%3};"               \
            : "+f"(C0), "+f"(C1), "+f"(C2), "+f"(C3)                              \
            : "r"(A0r), "r"(A1r), "r"(A2r), "r"(A3r), "r"(b0), "r"(b1));          \
    }

#pragma unroll 1
    for (int ntg = 0; ntg < 4; ntg++) {
        const int n0 = ntg * 32;
        float c00 = 0.f, c01 = 0.f, c02 = 0.f, c03 = 0.f;
        float c10 = 0.f, c11 = 0.f, c12 = 0.f, c13 = 0.f;
        float c20 = 0.f, c21 = 0.f, c22 = 0.f, c23 = 0.f;
        float c30 = 0.f, c31 = 0.f, c32 = 0.f, c33 = 0.f;

#pragma unroll 1
        for (int k0 = 0; k0 < NDIM; k0 += 32) {
            LOAD_A(k0,      p0, p1, p2, p3)
            LOAD_A(k0 + 16, q0, q1, q2, q3)

            MMA_STEP(k0, p0, p1, p2, p3, c00, c01, c02, c03, n0)
            MMA_STEP(k0, p0, p1, p2, p3, c10, c11, c12, c13, n0 + 8)
            MMA_STEP(k0, p0, p1, p2, p3, c20, c21, c22, c23, n0 + 16)
            MMA_STEP(k0, p0, p1, p2, p3, c30, c31, c32, c33, n0 + 24)

            MMA_STEP(k0 + 16, q0, q1, q2, q3, c00, c01, c02, c03, n0)
            MMA_STEP(k0 + 16, q0, q1, q2, q3, c10, c11, c12, c13, n0 + 8)
            MMA_STEP(k0 + 16, q0, q1, q2, q3, c20, c21, c22, c23, n0 + 16)
            MMA_STEP(k0 + 16, q0, q1, q2, q3, c30, c31, c32, c33, n0 + 24)
        }

        const int colb = n0 + 2 * t;
        if (row0 < n_rows) {
            __half* zp = g_z_h + (size_t)row0 * NDIM;
            *(__half2*)(zp + colb)      = __floats2half2_rn(c00, c01);
            *(__half2*)(zp + colb + 8)  = __floats2half2_rn(c10, c11);
            *(__half2*)(zp + colb + 16) = __floats2half2_rn(c20, c21);
            *(__half2*)(zp + colb + 24) = __floats2half2_rn(c30, c31);
        }
        if (row1 < n_rows) {
            __half* zp = g_z_h + (size_t)row1 * NDIM;
            *(__half2*)(zp + colb)      = __floats2half2_rn(c02, c03);
            *(__half2*)(zp + colb + 8)  = __floats2half2_rn(c12, c13);
            *(__half2*)(zp + colb + 16) = __floats2half2_rn(c22, c23);
            *(__half2*)(zp + colb + 24) = __floats2half2_rn(c32, c33);
        }
    }
#undef LOAD_A
#undef MMA_STEP
}

// ---------------------------------------------------------------------------
// Kernel 3: per-edge dot on fp16 tables (unchanged from the 155.6us pass).
// ---------------------------------------------------------------------------
__device__ __forceinline__ float dot8h(float4 a, float4 v) {
    const __half2* ah = (const __half2*)&a;
    const __half2* vh = (const __half2*)&v;
    __half2 p0 = __hmul2(ah[0], vh[0]);
    __half2 p1 = __hmul2(ah[1], vh[1]);
    __half2 p2 = __hmul2(ah[2], vh[2]);
    __half2 p3 = __hmul2(ah[3], vh[3]);
    float2 q0 = __half22float2(p0);
    float2 q1 = __half22float2(p1);
    float2 q2 = __half22float2(p2);
    float2 q3 = __half22float2(p3);
    return ((q0.x + q0.y) + (q1.x + q1.y)) + ((q2.x + q2.y) + (q3.x + q3.y));
}

#define EDGES_PER_WARP 8

__global__ void __launch_bounds__(256) edge_dot_kernel(
    const void* __restrict__ eli_raw,
    const float* __restrict__ bias,
    float* __restrict__ out,
    int E, unsigned int Nm1) {
    const int gwarp = (blockIdx.x * blockDim.x + threadIdx.x) >> 5;
    const int lane  = threadIdx.x & 31;
    const int half  = lane >> 4;
    const int sub   = lane & 15;

    const int e0 = gwarp * EDGES_PER_WARP;
    if (e0 >= E) return;

    const int is64 = g_idx_is64;
    const long long* eli64 = (const long long*)eli_raw;
    const int*       eli32 = (const int*)eli_raw;

    unsigned int sIdx[4], tIdx[4];
    int eidx[4];
#pragma unroll
    for (int j = 0; j < 4; j++) {
        int e = min(e0 + 2 * j + half, E - 1);   // tail-safe duplicate work
        eidx[j] = e;
        unsigned int s, t;
        if (is64) {
            s = (unsigned int)__ldg(&eli64[e]);
            t = (unsigned int)__ldg(&eli64[(long long)E + e]);
        } else {
            s = (unsigned int)__ldg(&eli32[e]);
            t = (unsigned int)__ldg(&eli32[(long long)E + e]);
        }
        sIdx[j] = min(s, Nm1);
        tIdx[j] = min(t, Nm1);
    }

    float4 a[4], v[4];
#pragma unroll
    for (int j = 0; j < 4; j++) {
        a[j] = __ldg((const float4*)(g_xs_h + ((size_t)sIdx[j] << 7) + (sub << 3)));
        v[j] = __ldg((const float4*)(g_z_h  + ((size_t)tIdx[j] << 7) + (sub << 3)));
    }

    const float bv = __ldg(bias);

#pragma unroll
    for (int j = 0; j < 4; j++) {
        float acc = dot8h(a[j], v[j]);
#pragma unroll
        for (int o = 8; o > 0; o >>= 1)
            acc += __shfl_down_sync(0xFFFFFFFFu, acc, o, 16);
        if (sub == 0)
            out[eidx[j]] = acc + bv;   // tail duplicates write identical values
    }
}

// ---------------------------------------------------------------------------
extern "C" void kernel_launch(void* const* d_in, const int* in_sizes, int n_in,
                              void* d_out, int out_size) {
    const float* x_source = nullptr;
    const float* x_target = nullptr;
    const void*  eli      = nullptr;
    const float* W        = nullptr;
    const float* bias     = nullptr;
    int N = 0;
    const int E = out_size;

    for (int i = 0; i < n_in; i++) {
        int sz = in_sizes[i];
        if (sz == NDIM * NDIM)      W    = (const float*)d_in[i];
        else if (sz == 1)           bias = (const float*)d_in[i];
        else if (sz == 2 * E)       eli  = d_in[i];
        else {
            if (!x_source) { x_source = (const float*)d_in[i]; N = sz / NDIM; }
            else           { x_target = (const float*)d_in[i]; }
        }
    }

    float* out = (float*)d_out;

    // 0) detect index dtype
    int nwords = 2 * E; if (nwords > 4096) nwords = 4096;
    detect_idx_kernel<<<1, 256>>>((const int*)eli, nwords);

    // 1) convert x_source -> fp16
    int n_elem4 = (N * NDIM) / 4;
    convert_xs_kernel<<<(n_elem4 + 255) / 256, 256>>>(x_source, n_elem4);

    // 2) z = xt @ W^T via tensor cores, A staged in dynamic shared (68 KB)
    const int dyn_smem = 2 * NDIM * APAD * (int)sizeof(__half);
    static int attr_set = 0;   // idempotent attribute set (host-side, benign)
    if (!attr_set) {
        cudaFuncSetAttribute(gemm_mma_kernel,
                             cudaFuncAttributeMaxDynamicSharedMemorySize, dyn_smem);
        attr_set = 1;
    }
    gemm_mma_kernel<<<(N + 127) / 128, 256, dyn_smem>>>(x_target, W, N);

    // 3) per-edge gather + dot
    int warps_needed = (E + EDGES_PER_WARP - 1) / EDGES_PER_WARP;
    int nblocks = (warps_needed + 7) / 8;
    edge_dot_kernel<<<nblocks, 256>>>(eli, bias, out, E, (unsigned int)(N - 1));
}

// round 15
// speedup vs baseline: 1.1369x; 1.0149x over previous
#include <cuda_runtime.h>
#include <cuda_fp16.h>
#include <cstdint>

#define NDIM 128
#define MAX_NODES 100000
#define APAD 136   // smem row stride in halves (128 + 8): conflict-free fragments

// Scratch: fp16 z table, fp16 x_source copy, dtype flag.
__device__ __half g_z_h[MAX_NODES * NDIM];    // 25.6 MB
__device__ __half g_xs_h[MAX_NODES * NDIM];   // 25.6 MB
__device__ int    g_idx_is64;

// ---------------------------------------------------------------------------
// Kernel 1: convert x_source -> fp16 (vectorized x4)
//  + block 0: index-dtype detection (int64 values < 2^31 -> odd words all 0)
// ---------------------------------------------------------------------------
__global__ void __launch_bounds__(256) convert_xs_kernel(const float* __restrict__ xs,
                                                         int n_elem4,
                                                         const int* __restrict__ eli_words,
                                                         int nwords) {
    if (blockIdx.x == 0) {
        __shared__ int s_any_nonzero;
        if (threadIdx.x == 0) s_any_nonzero = 0;
        __syncthreads();
        for (int i = 1 + 2 * threadIdx.x; i < nwords; i += 2 * blockDim.x) {
            if (eli_words[i] != 0) { s_any_nonzero = 1; break; }
        }
        __syncthreads();
        if (threadIdx.x == 0) g_idx_is64 = (s_any_nonzero == 0) ? 1 : 0;
    }

    int i = blockIdx.x * blockDim.x + threadIdx.x;
    if (i >= n_elem4) return;
    float4 v = *(const float4*)(xs + (size_t)i * 4);
    *(__half2*)(g_xs_h + (size_t)i * 4)     = __floats2half2_rn(v.x, v.y);
    *(__half2*)(g_xs_h + (size_t)i * 4 + 2) = __floats2half2_rn(v.z, v.w);
}

// ---------------------------------------------------------------------------
// Kernel 2: tensor-core GEMM  z[m][d] = sum_f xt[m][f] * W[d][f]
// mma.sync.m16n8k16.row.col.f32.f16.f16.f32
// A tile STAGED in shared via bulk coalesced float4 loads (MLP 16).
// 16 NAMED SCALAR accumulators (register arrays => lmem => 128MiB violation).
// Dynamic smem: A[128][136] + W[128][136] fp16 = 68 KB.
// Block: 256 thr = 8 warps x 16 rows = 128 rows/block.
// ---------------------------------------------------------------------------
__global__ void __launch_bounds__(256) gemm_mma_kernel(const float* __restrict__ xt,
                                                       const float* __restrict__ W,
                                                       int n_rows) {
    extern __shared__ __half smem[];
    __half* A_sh = smem;                 // [128][APAD]
    __half* W_sh = smem + NDIM * APAD;   // [128][APAD]

    const int tid = threadIdx.x;
    const int block_base = blockIdx.x * 128;

    // --- stage W (fp32 -> fp16) ---
    for (int i = tid; i < NDIM * NDIM; i += 256) {
        int r = i >> 7;
        int c = i & (NDIM - 1);
        W_sh[r * APAD + c] = __float2half_rn(W[i]);
    }

    // --- stage A tile: 128 rows x 32 float4 = 4096 chunks, 16 per thread ---
#pragma unroll 4
    for (int i = tid; i < 128 * 32; i += 256) {
        int r  = i >> 5;          // local row 0..127
        int c4 = i & 31;          // float4 index 0..31
        int grow = block_base + r;
        if (grow >= n_rows) grow = n_rows - 1;   // clamp (stores guarded later)
        float4 v = *(const float4*)(xt + (size_t)grow * NDIM + c4 * 4);
        __half2 h0 = __floats2half2_rn(v.x, v.y);
        __half2 h1 = __floats2half2_rn(v.z, v.w);
        __half* p = A_sh + r * APAD + c4 * 4;
        *(__half2*)(p)     = h0;
        *(__half2*)(p + 2) = h1;
    }
    __syncthreads();

    const int warp = tid >> 5;
    const int lane = tid & 31;
    const int g = lane >> 2;        // 0..7
    const int t = lane & 3;         // 0..3
    const int row_base = block_base + warp * 16;
    if (row_base >= n_rows) return;

    const __half* Arow0 = A_sh + (warp * 16 + g)     * APAD + 2 * t;
    const __half* Arow1 = A_sh + (warp * 16 + g + 8) * APAD + 2 * t;
    const int row0 = row_base + g;
    const int row1 = row_base + g + 8;

#define LOAD_A(k0, a0, a1, a2, a3)                                   \
    unsigned int a0, a1, a2, a3;                                      \
    {                                                                 \
        a0 = *(const unsigned int*)(Arow0 + (k0));                    \
        a1 = *(const unsigned int*)(Arow1 + (k0));                    \
        a2 = *(const unsigned int*)(Arow0 + (k0) + 8);                \
        a3 = *(const unsigned int*)(Arow1 + (k0) + 8);                \
    }

#define MMA_STEP(k0, A0r, A1r, A2r, A3r, C0, C1, C2, C3, NROW)                    \
    {                                                                             \
        unsigned int b0 = *(const unsigned int*)(W_sh + ((NROW) + g) * APAD + (k0) + 2 * t);     \
        unsigned int b1 = *(const unsigned int*)(W_sh + ((NROW) + g) * APAD + (k0) + 2 * t + 8); \
        asm volatile(                                                             \
            "mma.sync.aligned.m16n8k16.row.col.f32.f16.f16.f32 "                  \
            "{%0,%1,%2,%3}, {%4,%5,%6,%7}, {%8,%9}, {%0,%1,%2,%3};"               \
            : "+f"(C0), "+f"(C1), "+f"(C2), "+f"(C3)                              \
            : "r"(A0r), "r"(A1r), "r"(A2r), "r"(A3r), "r"(b0), "r"(b1));          \
    }

#pragma unroll 1
    for (int ntg = 0; ntg < 4; ntg++) {
        const int n0 = ntg * 32;
        float c00 = 0.f, c01 = 0.f, c02 = 0.f, c03 = 0.f;
        float c10 = 0.f, c11 = 0.f, c12 = 0.f, c13 = 0.f;
        float c20 = 0.f, c21 = 0.f, c22 = 0.f, c23 = 0.f;
        float c30 = 0.f, c31 = 0.f, c32 = 0.f, c33 = 0.f;

#pragma unroll 1
        for (int k0 = 0; k0 < NDIM; k0 += 32) {
            LOAD_A(k0,      p0, p1, p2, p3)
            LOAD_A(k0 + 16, q0, q1, q2, q3)

            MMA_STEP(k0, p0, p1, p2, p3, c00, c01, c02, c03, n0)
            MMA_STEP(k0, p0, p1, p2, p3, c10, c11, c12, c13, n0 + 8)
            MMA_STEP(k0, p0, p1, p2, p3, c20, c21, c22, c23, n0 + 16)
            MMA_STEP(k0, p0, p1, p2, p3, c30, c31, c32, c33, n0 + 24)

            MMA_STEP(k0 + 16, q0, q1, q2, q3, c00, c01, c02, c03, n0)
            MMA_STEP(k0 + 16, q0, q1, q2, q3, c10, c11, c12, c13, n0 + 8)
            MMA_STEP(k0 + 16, q0, q1, q2, q3, c20, c21, c22, c23, n0 + 16)
            MMA_STEP(k0 + 16, q0, q1, q2, q3, c30, c31, c32, c33, n0 + 24)
        }

        const int colb = n0 + 2 * t;
        if (row0 < n_rows) {
            __half* zp = g_z_h + (size_t)row0 * NDIM;
            *(__half2*)(zp + colb)      = __floats2half2_rn(c00, c01);
            *(__half2*)(zp + colb + 8)  = __floats2half2_rn(c10, c11);
            *(__half2*)(zp + colb + 16) = __floats2half2_rn(c20, c21);
            *(__half2*)(zp + colb + 24) = __floats2half2_rn(c30, c31);
        }
        if (row1 < n_rows) {
            __half* zp = g_z_h + (size_t)row1 * NDIM;
            *(__half2*)(zp + colb)      = __floats2half2_rn(c02, c03);
            *(__half2*)(zp + colb + 8)  = __floats2half2_rn(c12, c13);
            *(__half2*)(zp + colb + 16) = __floats2half2_rn(c22, c23);
            *(__half2*)(zp + colb + 24) = __floats2half2_rn(c32, c33);
        }
    }
#undef LOAD_A
#undef MMA_STEP
}

// ---------------------------------------------------------------------------
// Kernel 3: per-edge dot on fp16 tables.
// vs R14: indices fetched as ONE coalesced vector (lanes 0-7 src, 8-15 tgt)
// and distributed by shuffle (8 LDG -> 2 LDG + 8 SHFL), clamp hoisted,
// streaming stores (__stcs).
// ---------------------------------------------------------------------------
__device__ __forceinline__ float dot8h(float4 a, float4 v) {
    const __half2* ah = (const __half2*)&a;
    const __half2* vh = (const __half2*)&v;
    __half2 p0 = __hmul2(ah[0], vh[0]);
    __half2 p1 = __hmul2(ah[1], vh[1]);
    __half2 p2 = __hmul2(ah[2], vh[2]);
    __half2 p3 = __hmul2(ah[3], vh[3]);
    float2 q0 = __half22float2(p0);
    float2 q1 = __half22float2(p1);
    float2 q2 = __half22float2(p2);
    float2 q3 = __half22float2(p3);
    return ((q0.x + q0.y) + (q1.x + q1.y)) + ((q2.x + q2.y) + (q3.x + q3.y));
}

#define EDGES_PER_WARP 8

__global__ void __launch_bounds__(256) edge_dot_kernel(
    const void* __restrict__ eli_raw,
    const float* __restrict__ bias,
    float* __restrict__ out,
    int E, unsigned int Nm1) {
    const int gwarp = (blockIdx.x * blockDim.x + threadIdx.x) >> 5;
    const int lane  = threadIdx.x & 31;
    const int half  = lane >> 4;
    const int sub   = lane & 15;

    const int e0 = gwarp * EDGES_PER_WARP;
    if (e0 >= E) return;

    const int is64 = g_idx_is64;

    // coalesced index fetch: lanes 0-7 src[e0..e0+7], lanes 8-15 tgt[e0..e0+7]
    unsigned int myIdx = 0;
    if (lane < 16) {
        int e = min(e0 + (lane & 7), E - 1);
        if (is64) {
            const long long* p = (const long long*)eli_raw;
            myIdx = (unsigned int)__ldg(&p[(lane < 8 ? 0ll : (long long)E) + e]);
        } else {
            const int* p = (const int*)eli_raw;
            myIdx = (unsigned int)__ldg(&p[(lane < 8 ? 0 : E) + e]);
        }
        myIdx = min(myIdx, Nm1);
    }

    unsigned int sIdx[4], tIdx[4];
#pragma unroll
    for (int j = 0; j < 4; j++) {
        sIdx[j] = __shfl_sync(0xFFFFFFFFu, myIdx, 2 * j + half);
        tIdx[j] = __shfl_sync(0xFFFFFFFFu, myIdx, 8 + 2 * j + half);
    }

    float4 a[4], v[4];
#pragma unroll
    for (int j = 0; j < 4; j++) {
        a[j] = __ldg((const float4*)(g_xs_h + ((size_t)sIdx[j] << 7) + (sub << 3)));
        v[j] = __ldg((const float4*)(g_z_h  + ((size_t)tIdx[j] << 7) + (sub << 3)));
    }

    const float bv = __ldg(bias);

#pragma unroll
    for (int j = 0; j < 4; j++) {
        float acc = dot8h(a[j], v[j]);
#pragma unroll
        for (int o = 8; o > 0; o >>= 1)
            acc += __shfl_down_sync(0xFFFFFFFFu, acc, o, 16);
        if (sub == 0) {
            int e = min(e0 + 2 * j + half, E - 1);  // tail duplicates identical
            __stcs(&out[e], acc + bv);
        }
    }
}

// ---------------------------------------------------------------------------
extern "C" void kernel_launch(void* const* d_in, const int* in_sizes, int n_in,
                              void* d_out, int out_size) {
    const float* x_source = nullptr;
    const float* x_target = nullptr;
    const void*  eli      = nullptr;
    const float* W        = nullptr;
    const float* bias     = nullptr;
    int N = 0;
    const int E = out_size;

    for (int i = 0; i < n_in; i++) {
        int sz = in_sizes[i];
        if (sz == NDIM * NDIM)      W    = (const float*)d_in[i];
        else if (sz == 1)           bias = (const float*)d_in[i];
        else if (sz == 2 * E)       eli  = d_in[i];
        else {
            if (!x_source) { x_source = (const float*)d_in[i]; N = sz / NDIM; }
            else           { x_target = (const float*)d_in[i]; }
        }
    }

    float* out = (float*)d_out;

    int nwords = 2 * E; if (nwords > 4096) nwords = 4096;
    int n_elem4 = (N * NDIM) / 4;

    // 1) convert x_source -> fp16 (+ idx dtype detect in block 0)
    convert_xs_kernel<<<(n_elem4 + 255) / 256, 256>>>(x_source, n_elem4,
                                                      (const int*)eli, nwords);

    // 2) z = xt @ W^T via tensor cores, A staged in dynamic shared (68 KB)
    const int dyn_smem = 2 * NDIM * APAD * (int)sizeof(__half);
    static int attr_set = 0;
    if (!attr_set) {
        cudaFuncSetAttribute(gemm_mma_kernel,
                             cudaFuncAttributeMaxDynamicSharedMemorySize, dyn_smem);
        attr_set = 1;
    }
    gemm_mma_kernel<<<(N + 127) / 128, 256, dyn_smem>>>(x_target, W, N);

    // 3) per-edge gather + dot
    int warps_needed = (E + EDGES_PER_WARP - 1) / EDGES_PER_WARP;
    int nblocks = (warps_needed + 7) / 8;
    edge_dot_kernel<<<nblocks, 256>>>(eli, bias, out, E, (unsigned int)(N - 1));
}